// round 9
// baseline (speedup 1.0000x reference)
#include <cuda_runtime.h>
#include <cstdint>
#include <math.h>

// Problem dims (SimpleLSTM): B=64, T=512, D=1024, H=1024
#define B_  64
#define T_  512
#define D_  1024
#define H_  1024
#define G4_ 4096   // 4*H

// ---------------- scratch (device globals: allocation-free) ----------------
__device__ float g_xproj[(size_t)T_ * B_ * G4_];      // [T*B][4H] fp32 (m = t*64+b)
__device__ float g_xsA[(size_t)2048 * 128 * 32 * 4];  // xs in A-frag layout (128MB)
__device__ float g_WxB[(size_t)128 * 128 * 2 * 32 * 4];// Wx in B-frag layout (16MB)
// hidden state, A-frag permuted, f4 layout [ki(128)][strip(4)][lane(32)], v(4)
__device__ float g_hperm[2][B_ * H_];

// hierarchical barrier state (counters return to 0 after each use -> replay-safe)
struct PadCnt { unsigned v; unsigned pad[31]; };   // 128B spacing
__device__ PadCnt g_cnt1[8];
__device__ unsigned g_cnt2 = 0;
__device__ unsigned g_bar_gen = 0;

// ---------------- helpers ----------------
__device__ __forceinline__ void cp_async16(void* dst, const void* src) {
    uint32_t s = (uint32_t)__cvta_generic_to_shared(dst);
    asm volatile("cp.async.cg.shared.global [%0], [%1], 16;\n" :: "r"(s), "l"(src));
}
__device__ __forceinline__ void cp_commit() { asm volatile("cp.async.commit_group;\n"); }
template<int N>
__device__ __forceinline__ void cp_wait() { asm volatile("cp.async.wait_group %0;\n" :: "n"(N)); }

__device__ __forceinline__ float tf32_rnaf(float x) {
    unsigned r;
    asm("cvt.rna.tf32.f32 %0, %1;" : "=r"(r) : "f"(x));
    return __uint_as_float(r);
}
__device__ __forceinline__ void mma_tf32(float4& d, const uint4& a,
                                         unsigned b0, unsigned b1) {
    asm volatile(
        "mma.sync.aligned.m16n8k8.row.col.f32.tf32.tf32.f32 "
        "{%0,%1,%2,%3}, {%4,%5,%6,%7}, {%8,%9}, {%0,%1,%2,%3};"
        : "+f"(d.x), "+f"(d.y), "+f"(d.z), "+f"(d.w)
        : "r"(a.x), "r"(a.y), "r"(a.z), "r"(a.w), "r"(b0), "r"(b1));
}
__device__ __forceinline__ float sigmoid_f(float x) {
    return __fdividef(1.0f, 1.0f + __expf(-x));
}
__device__ __forceinline__ float tanh_f(float x) {
    return __fdividef(2.0f, 1.0f + __expf(-2.0f * x)) - 1.0f;
}
__device__ __forceinline__ uint32_t smem_u32_of(const void* p) {
    return (uint32_t)__cvta_generic_to_shared(p);
}
__device__ __forceinline__ uint32_t cluster_rank() {
    uint32_t r;
    asm("mov.u32 %0, %%cluster_ctarank;" : "=r"(r));
    return r;
}

// ---- mbarrier ops ----
#define MBAR_INIT(addr, cnt) \
    asm volatile("mbarrier.init.shared.b64 [%0], %1;" :: "r"(addr), "r"(cnt) : "memory")
#define MBAR_ARRIVE_EXPECT_TX(addr, tx) \
    asm volatile("mbarrier.arrive.expect_tx.shared.b64 _, [%0], %1;" \
        :: "r"(addr), "r"(tx) : "memory")
#define MBAR_ARRIVE_CLUSTER(addr, rank) \
    asm volatile("{\n\t.reg .b32 ra;\n\t" \
        "mapa.shared::cluster.u32 ra, %0, %1;\n\t" \
        "mbarrier.arrive.shared::cluster.b64 _, [ra];\n\t}" \
        :: "r"(addr), "r"(rank) : "memory")
#define MBAR_WAIT(addr, parity) do { \
    uint32_t _m = (addr), _p = (parity), _d; \
    asm volatile("{\n\t.reg .pred p;\n\t" \
        "mbarrier.try_wait.parity.acquire.cta.shared::cta.b64 p, [%1], %2;\n\t" \
        "selp.b32 %0, 1, 0, p;\n\t}" : "=r"(_d) : "r"(_m), "r"(_p) : "memory"); \
    if (!_d) { \
        asm volatile("{\n\t.reg .pred P1;\n\t" \
            "WL_%=:\n\t" \
            "mbarrier.try_wait.parity.acquire.cta.shared::cta.b64 P1, [%0], %1, 0x989680;\n\t" \
            "@P1 bra.uni WD_%=;\n\t" \
            "bra.uni WL_%=;\n\t" \
            "WD_%=:\n\t}" :: "r"(_m), "r"(_p) : "memory"); \
    } \
} while (0)
// 1D bulk multicast: global -> shared::cluster (all CTAs in mask, same offset)
#define BULK_MCAST(dst_smem, src_gmem, bytes, mbar_smem, mask) \
    asm volatile("cp.async.bulk.shared::cluster.global.mbarrier::complete_tx::bytes" \
        ".multicast::cluster [%0], [%1], %2, [%3], %4;" \
        :: "r"(dst_smem), "l"(src_gmem), "r"(bytes), "r"(mbar_smem), \
           "h"((unsigned short)(mask)) : "memory")

// hierarchical arrive: ~24 serialized atomic slots instead of 128.
__device__ __forceinline__ void bar_arrive(int bIdx) {
    __threadfence();                               // release prior global stores
    unsigned o = atomicAdd(&g_cnt1[bIdx >> 4].v, 1u);
    if (o == 15u) {
        unsigned o2 = atomicAdd(&g_cnt2, 1u);
        if (o2 == 7u) {
            #pragma unroll
            for (int i = 0; i < 8; i++) atomicExch(&g_cnt1[i].v, 0u);
            atomicExch(&g_cnt2, 0u);
            __threadfence();
            atomicAdd(&g_bar_gen, 1u);
        }
    }
}

// ============================================================================
// P1: permute xs -> g_xsA (A-frag layout, tf32-rounded).  (round-8, proven)
// ============================================================================
__global__ void __launch_bounds__(256) permA_kernel(const float* __restrict__ xs) {
    size_t x = (size_t)blockIdx.x * 256 + threadIdx.x;   // < 2048*128*32
    int lane  = (int)(x & 31);
    int ki    = (int)((x >> 5) & 127);
    int strip = (int)(x >> 12);
    int r  = strip * 16 + (lane >> 2);
    int k  = ki * 8 + (lane & 3);
    auto src = [&](int m, int kk) -> float {
        int b = m & 63, t = m >> 6;
        return xs[((size_t)b * T_ + t) * D_ + kk];
    };
    float4 v;
    v.x = tf32_rnaf(src(r,     k));
    v.y = tf32_rnaf(src(r + 8, k));
    v.z = tf32_rnaf(src(r,     k + 4));
    v.w = tf32_rnaf(src(r + 8, k + 4));
    *reinterpret_cast<float4*>(g_xsA + x * 4) = v;
}

// ============================================================================
// P2: permute Wx -> g_WxB (B-frag layout, tf32-rounded).  (round-8, proven)
// ============================================================================
__global__ void __launch_bounds__(256) permB_kernel(const float* __restrict__ Wx) {
    size_t y = (size_t)blockIdx.x * 256 + threadIdx.x;   // < 128*128*2*32
    int lane = (int)(y & 31);
    int nh   = (int)((y >> 5) & 1);
    int ki   = (int)((y >> 6) & 127);
    int ng   = (int)(y >> 13);
    int c = ng * 32 + nh * 16 + (lane >> 2);
    int k = ki * 8 + (lane & 3);
    float4 v;
    v.x = tf32_rnaf(Wx[(size_t)k * G4_ + c]);
    v.y = tf32_rnaf(Wx[(size_t)(k + 4) * G4_ + c]);
    v.z = tf32_rnaf(Wx[(size_t)k * G4_ + c + 8]);
    v.w = tf32_rnaf(Wx[(size_t)(k + 4) * G4_ + c + 8]);
    *reinterpret_cast<float4*>(g_WxB + y * 4) = v;
}

// ============================================================================
// Kernel G: xproj = xsA @ WxB  (round-8, proven, byte-identical)
// ============================================================================
__global__ void __launch_bounds__(256) xproj_kernel() {
    extern __shared__ float4 smG[];   // 3 stages x (A 2048 + B 2048) f4
    const int tid  = threadIdx.x;
    const int lane = tid & 31;
    const int w    = tid >> 5;
    const int wm   = w >> 2;
    const int wn   = w & 3;
    const int mt   = blockIdx.y;
    const int nt   = blockIdx.x;

    const float4* xsA = reinterpret_cast<const float4*>(g_xsA);
    const float4* WxB = reinterpret_cast<const float4*>(g_WxB);

    auto issue = [&](int ch) {
        float4* stA = smG + (ch % 3) * 4096;
        float4* stB = stA + 2048;
        #pragma unroll
        for (int it = 0; it < 8; it++) {
            int lin = tid + it * 256;
            int ln  = lin & 31;
            int dki = (lin >> 5) & 7;
            int st  = lin >> 8;
            cp_async16(&stA[lin],
                       &xsA[((size_t)(mt * 8 + st) * 128 + ch * 8 + dki) * 32 + ln]);
        }
        #pragma unroll
        for (int it = 0; it < 8; it++) {
            int lin = tid + it * 256;
            int ln  = lin & 31;
            int nh  = (lin >> 5) & 1;
            int dki = (lin >> 6) & 7;
            int ng  = lin >> 9;
            cp_async16(&stB[lin],
                       &WxB[(((size_t)(nt * 4 + ng) * 128 + ch * 8 + dki) * 2 + nh) * 32 + ln]);
        }
    };

    float4 acc[4][4];
    #pragma unroll
    for (int s = 0; s < 4; s++)
        #pragma unroll
        for (int g = 0; g < 4; g++)
            acc[s][g] = make_float4(0.f, 0.f, 0.f, 0.f);

    issue(0); cp_commit();
    issue(1); cp_commit();

    #pragma unroll 1
    for (int ch = 0; ch < 16; ch++) {
        __syncthreads();
        if (ch + 2 < 16) { issue(ch + 2); cp_commit(); }
        if (ch < 14) cp_wait<2>(); else if (ch == 14) cp_wait<1>(); else cp_wait<0>();
        __syncthreads();

        const float4* stA = smG + (ch % 3) * 4096;
        const float4* stB = stA + 2048;
        #pragma unroll
        for (int d = 0; d < 8; d++) {
            uint4 a[4];
            #pragma unroll
            for (int s = 0; s < 4; s++)
                a[s] = *reinterpret_cast<const uint4*>(
                    &stA[((wm * 4 + s) * 8 + d) * 32 + lane]);
            uint4 b0 = *reinterpret_cast<const uint4*>(&stB[((wn * 8 + d) * 2 + 0) * 32 + lane]);
            uint4 b1 = *reinterpret_cast<const uint4*>(&stB[((wn * 8 + d) * 2 + 1) * 32 + lane]);
            #pragma unroll
            for (int s = 0; s < 4; s++) {
                mma_tf32(acc[s][0], a[s], b0.x, b0.y);
                mma_tf32(acc[s][1], a[s], b0.z, b0.w);
                mma_tf32(acc[s][2], a[s], b1.x, b1.y);
                mma_tf32(acc[s][3], a[s], b1.z, b1.w);
            }
        }
    }

    int r  = lane >> 2;
    int c2 = (lane & 3) * 2;
    #pragma unroll
    for (int s = 0; s < 4; s++)
        #pragma unroll
        for (int g = 0; g < 4; g++) {
            size_t row = (size_t)mt * 128 + (wm * 4 + s) * 16 + r;
            size_t col = (size_t)nt * 128 + wn * 32 + g * 8 + c2;
            *reinterpret_cast<float2*>(g_xproj + row * G4_ + col) =
                make_float2(acc[s][g].x, acc[s][g].y);
            *reinterpret_cast<float2*>(g_xproj + (row + 8) * G4_ + col) =
                make_float2(acc[s][g].z, acc[s][g].w);
        }
}

// ============================================================================
// Kernel B: persistent LSTM scan, 128 CTAs x 128 thr, CLUSTERS OF 4.
//   Identical compute structure to round 7/8 (k-quarter warps, sg reduce,
//   hierarchical global barrier). ONLY the h load path changed: each 4KB
//   h-chunk is fetched ONCE per cluster via cp.async.bulk multicast (rotating
//   producer CTA (kq+ci)&3), delivered to all 4 CTAs' stage smem with
//   mbarrier complete_tx. full[kq][s]: local, count=1 + 4096 tx per phase.
//   empty[kq][s]: lives in producer CTA (kq+s)&3, count=4 (cluster arrives).
//   4 phases/stage/step (even) -> parities independent of t.
// ============================================================================
__global__ void __launch_bounds__(128, 1) __cluster_dims__(4, 1, 1)
lstm_scan_kernel(
    const float* __restrict__ c0, const float* __restrict__ h0,
    const float* __restrict__ Wh, const float* __restrict__ bias,
    float* __restrict__ out)
{
    extern __shared__ float sm[];
    // Whs: floats [0, 32768)          (128KB)
    // hs:  floats [32768, 49152)      (64KB: [kq(4)][stage(4)][256 f4])
    // sg:  floats [49152, 57856)      (34.8KB: [kq(4)][row(64) stride 34])
    // mbar: bytes [231424, 231680)    (full[16] u64, empty[16] u64)
    float*  Whs_f = sm;
    float4* Whs   = reinterpret_cast<float4*>(sm);
    float4* hs    = reinterpret_cast<float4*>(sm + 32768);
    float*  sg    = sm + 49152;

    const int tid  = threadIdx.x;
    const int lane = tid & 31;
    const int kq   = tid >> 5;          // warp id == k-quarter
    const int bIdx = blockIdx.x;
    const int j0   = bIdx * 8;
    const uint32_t rank = cluster_rank();   // 0..3

    const uint32_t smem_base = smem_u32_of(sm);
    const uint32_t mb_full  = smem_base + 231424u;   // + (kq*4+s)*8
    const uint32_t mb_empty = smem_base + 231552u;   // + (kq*4+s)*8
    const uint32_t hs_smem  = smem_base + 131072u;   // byte addr of hs

    // ---- build Whs (tf32, B-frag permuted) — identical to round 5/7/8
    for (int i = tid; i < 32768; i += 128) {
        int v   = i & 3;
        int ln  = (i >> 2) & 31;
        int nh  = (i >> 7) & 1;
        int ki2 = (i >> 8) & 31;
        int kqq = i >> 13;
        int k = (kqq * 32 + ki2) * 8 + (ln & 3) + ((v & 1) << 2);
        int c = nh * 16 + (ln >> 2) + ((v >> 1) << 3);
        int gate = c >> 3, jc = c & 7;
        Whs_f[i] = tf32_rnaf(__ldg(Wh + (size_t)k * G4_ + gate * H_ + j0 + jc));
    }

    // ---- per-thread ownership: column j = j0 + (tid&7), rows b_q = rbase+16q
    const int rbase = tid >> 3;
    const int jj    = tid & 7;
    const int j     = j0 + jj;
    int bq[4];
    #pragma unroll
    for (int q = 0; q < 4; q++) bq[q] = rbase + q * 16;

    float creg[4], bia[4];
    #pragma unroll
    for (int g = 0; g < 4; g++) bia[g] = __ldg(bias + g * H_ + j);
    #pragma unroll
    for (int q = 0; q < 4; q++) creg[q] = __ldg(c0 + (size_t)bq[q] * H_ + j);

    const int lane_h = (rbase & 7) * 4 + (jj & 3);
    const int v_h    = ((rbase >> 3) & 1) | ((jj >> 2) << 1);

    // ---- init g_hperm[0] = tf32(h0)
    #pragma unroll
    for (int q = 0; q < 4; q++) {
        size_t f4 = ((size_t)bIdx * 4 + q) * 32 + lane_h;
        g_hperm[0][f4 * 4 + v_h] = tf32_rnaf(__ldg(h0 + (size_t)bq[q] * H_ + j));
    }

    // ---- xproj prefetch
    float xpr[4][4];
    auto prefetch_xp = [&](int t) {
        const float* xp = g_xproj + (size_t)t * B_ * G4_;
        #pragma unroll
        for (int q = 0; q < 4; q++)
            #pragma unroll
            for (int g = 0; g < 4; g++)
                xpr[q][g] = __ldg(xp + (size_t)bq[q] * G4_ + g * H_ + j);
    };
    prefetch_xp(0);

    // ---- init mbarriers
    if (tid == 0) {
        #pragma unroll
        for (int i = 0; i < 16; i++) {
            MBAR_INIT(mb_full + i * 8, 1u);
            MBAR_INIT(mb_empty + i * 8, 4u);
        }
    }
    __syncthreads();
    // arm phase 0 of this warp's full barriers
    if (lane == 0) {
        #pragma unroll
        for (int s = 0; s < 4; s++)
            MBAR_ARRIVE_EXPECT_TX(mb_full + ((kq << 2) + s) * 8, 4096u);
    }
    // cluster sync: mbarrier inits visible before any multicast targets them
    asm volatile("barrier.cluster.arrive.aligned;" ::: "memory");
    asm volatile("barrier.cluster.wait.aligned;" ::: "memory");

    // ---- initial global grid sync
    __syncthreads();
    {
        unsigned mygen = 0;
        if (tid == 0) {
            volatile unsigned* genp = &g_bar_gen;
            mygen = *genp;
            bar_arrive(bIdx);
            while (*genp == mygen) { }
            __threadfence();
        }
        __syncthreads();
    }

    for (int t = 0; t < T_; t++) {
        const float* hcur  = g_hperm[t & 1];
        float*       hnext = g_hperm[(t + 1) & 1];

        // producer: issue multicast for chunk ci of this warp's quarter.
        // stage s = ci&3; empty parity = ((ci>>2)+1)&1 (fresh-barrier trick).
        auto produce = [&](int ci) {
            int s = ci & 3;
            uint32_t eb = mb_empty + ((kq << 2) + s) * 8;
            MBAR_WAIT(eb, ((ci >> 2) + 1) & 1);
            uint32_t dst = hs_smem + (uint32_t)(kq * 1024 + s * 256) * 16u;
            const char* src = (const char*)hcur + (size_t)(kq * 32 + ci * 2) * 2048;
            BULK_MCAST(dst, src, 4096u, mb_full + ((kq << 2) + s) * 8, 0xF);
        };

        // preloop: issue chunks 0..2 (whoever owns them)
        if (lane == 0) {
            #pragma unroll
            for (int ci = 0; ci < 3; ci++)
                if (((kq + ci) & 3) == (int)rank) produce(ci);
        }

        float4 acc[4][4];   // [strip][gate-group]
        #pragma unroll
        for (int s = 0; s < 4; s++)
            #pragma unroll
            for (int g = 0; g < 4; g++)
                acc[s][g] = make_float4(0.f, 0.f, 0.f, 0.f);

        #pragma unroll 1
        for (int ch = 0; ch < 16; ch++) {
            if (lane == 0) {
                int ci = ch + 3;
                if (ci < 16 && ((kq + ci) & 3) == (int)rank) produce(ci);
            }
            int s = ch & 3;
            uint32_t fb = mb_full + ((kq << 2) + s) * 8;
            MBAR_WAIT(fb, (ch >> 2) & 1);
            if (lane == 0) MBAR_ARRIVE_EXPECT_TX(fb, 4096u);   // arm next phase

            const float4* st = hs + kq * 1024 + s * 256;
            #pragma unroll
            for (int d = 0; d < 2; d++) {
                int ki2 = ch * 2 + d;
                uint4 a[4];
                #pragma unroll
                for (int ss = 0; ss < 4; ss++)
                    a[ss] = *reinterpret_cast<const uint4*>(&st[(d * 4 + ss) * 32 + lane]);
                uint4 b0 = *reinterpret_cast<const uint4*>(
                    &Whs[((kq * 32 + ki2) * 2 + 0) * 32 + lane]);
                uint4 b1 = *reinterpret_cast<const uint4*>(
                    &Whs[((kq * 32 + ki2) * 2 + 1) * 32 + lane]);
                #pragma unroll
                for (int ss = 0; ss < 4; ss++) {
                    mma_tf32(acc[ss][0], a[ss], b0.x, b0.y);
                    mma_tf32(acc[ss][1], a[ss], b0.z, b0.w);
                    mma_tf32(acc[ss][2], a[ss], b1.x, b1.y);
                    mma_tf32(acc[ss][3], a[ss], b1.z, b1.w);
                }
            }
            // free stage: arrive on producer CTA's empty barrier
            if (lane == 0)
                MBAR_ARRIVE_CLUSTER(mb_empty + ((kq << 2) + s) * 8,
                                    (unsigned)((kq + s) & 3));
        }

        // ---- stage partials: sg[kq][row (stride 34)][col = gate*8 + jj]
        {
            int r  = lane >> 2;
            int c2 = (lane & 3) * 2;
            float* base = sg + (size_t)kq * 64 * 34;
            #pragma unroll
            for (int s = 0; s < 4; s++)
                #pragma unroll
                for (int g = 0; g < 4; g++) {
                    *reinterpret_cast<float2*>(base + (s * 16 + r) * 34 + g * 8 + c2) =
                        make_float2(acc[s][g].x, acc[s][g].y);
                    *reinterpret_cast<float2*>(base + (s * 16 + r + 8) * 34 + g * 8 + c2) =
                        make_float2(acc[s][g].z, acc[s][g].w);
                }
        }
        __syncthreads();

        // ---- reduce 4 k-quarters + fused elementwise (flax order i,f,g,o)
        float hnv[4];
        #pragma unroll
        for (int q = 0; q < 4; q++) {
            float gv[4];
            #pragma unroll
            for (int g = 0; g < 4; g++) {
                float sum = 0.f;
                #pragma unroll
                for (int kk = 0; kk < 4; kk++)
                    sum += sg[((size_t)kk * 64 + bq[q]) * 34 + g * 8 + jj];
                gv[g] = sum;
            }
            float pi = gv[0] + xpr[q][0] + bia[0];
            float pf = gv[1] + xpr[q][1] + bia[1];
            float pg = gv[2] + xpr[q][2] + bia[2];
            float po = gv[3] + xpr[q][3] + bia[3];
            float cn = sigmoid_f(pf) * creg[q] + sigmoid_f(pi) * tanh_f(pg);
            float hn = sigmoid_f(po) * tanh_f(cn);
            creg[q] = cn;
            hnv[q] = hn;
        }

        // ---- write hnext (tf32-rounded, permuted)
        #pragma unroll
        for (int q = 0; q < 4; q++) {
            size_t f4 = ((size_t)bIdx * 4 + q) * 32 + lane_h;
            hnext[f4 * 4 + v_h] = tf32_rnaf(hnv[q]);
        }

        // ---- global barrier arrive (hierarchical; releases h stores)
        __syncthreads();
        unsigned mygen = 0;
        if (tid == 0) {
            volatile unsigned* genp = &g_bar_gen;
            mygen = *genp;
            bar_arrive(bIdx);
        }

        // ---- hidden work between arrive and wait: ys stores + next prefetch
        #pragma unroll
        for (int q = 0; q < 4; q++)
            out[2 * B_ * H_ + ((size_t)bq[q] * T_ + t) * H_ + j] = hnv[q];
        if (t == T_ - 1) {
            #pragma unroll
            for (int q = 0; q < 4; q++)
                out[B_ * H_ + (size_t)bq[q] * H_ + j] = hnv[q];
        }
        if (t + 1 < T_) prefetch_xp(t + 1);

        // ---- barrier wait
        if (tid == 0) {
            volatile unsigned* genp = &g_bar_gen;
            while (*genp == mygen) { }
            __threadfence();                    // acquire
        }
        __syncthreads();
    }

    // cT
    #pragma unroll
    for (int q = 0; q < 4; q++)
        out[(size_t)bq[q] * H_ + j] = creg[q];

    // no CTA may exit while a peer's multicast could target its smem
    asm volatile("barrier.cluster.arrive.aligned;" ::: "memory");
    asm volatile("barrier.cluster.wait.aligned;" ::: "memory");
}

// ============================================================================
// Launch. Inputs: c0, h0, xs, Wx, Wh, b. Output fp32: [cT][hT][ys]
// ============================================================================
extern "C" void kernel_launch(void* const* d_in, const int* in_sizes, int n_in,
                              void* d_out, int out_size) {
    const float* c0   = (const float*)d_in[0];
    const float* h0   = (const float*)d_in[1];
    const float* xs   = (const float*)d_in[2];
    const float* Wx   = (const float*)d_in[3];
    const float* Wh   = (const float*)d_in[4];
    const float* bias = (const float*)d_in[5];
    float* out = (float*)d_out;

    constexpr int G_SMEM    = 3 * 4096 * 16;                       // 196,608 B
    constexpr int SCAN_SMEM = (32768 + 16384 + 8704) * 4 + 1024;   // 232,448 B
    cudaFuncSetAttribute(xproj_kernel,
                         cudaFuncAttributeMaxDynamicSharedMemorySize, G_SMEM);
    cudaFuncSetAttribute(lstm_scan_kernel,
                         cudaFuncAttributeMaxDynamicSharedMemorySize, SCAN_SMEM);

    permA_kernel<<<32768, 256>>>(xs);
    permB_kernel<<<4096, 256>>>(Wx);
    dim3 gridG(32, 256);
    xproj_kernel<<<gridG, 256, G_SMEM>>>();
    lstm_scan_kernel<<<128, 128, SCAN_SMEM>>>(c0, h0, Wh, bias, out);
}

// round 10
// speedup vs baseline: 1.4699x; 1.4699x over previous
#include <cuda_runtime.h>
#include <cuda_fp16.h>
#include <cstdint>
#include <math.h>

// Problem dims (SimpleLSTM): B=64, T=512, D=1024, H=1024
#define B_  64
#define T_  512
#define D_  1024
#define H_  1024
#define G4_ 4096   // 4*H

// ---------------- scratch (device globals: allocation-free) ----------------
__device__ float g_xproj[(size_t)T_ * B_ * G4_];      // [T*B][4H] fp32 (m = t*64+b)
__device__ float g_xsA[(size_t)2048 * 128 * 32 * 4];  // xs in A-frag layout (128MB)
__device__ float g_WxB[(size_t)128 * 128 * 2 * 32 * 4];// Wx in B-frag layout (16MB)
// hidden state in fp16 A-frag (m16n8k16) layout, double buffered:
//   uint4 index ((ki*4 + strip)*32 + lane), halves within:
//   v0={h[r][k],h[r][k+1]} v1={h[r+8][k],..} v2={h[r][k+8],..} v3={h[r+8][k+8],..}
//   r = strip*16 + (lane>>2), k = ki*16 + (lane&3)*2
__device__ __half g_hperm_h[2][B_ * H_];

// hierarchical barrier state (counters return to 0 after each use -> replay-safe)
struct PadCnt { unsigned v; unsigned pad[31]; };   // 128B spacing
__device__ PadCnt g_cnt1[8];
__device__ unsigned g_cnt2 = 0;
__device__ unsigned g_bar_gen = 0;

// ---------------- helpers ----------------
__device__ __forceinline__ void cp_async16(void* dst, const void* src) {
    uint32_t s = (uint32_t)__cvta_generic_to_shared(dst);
    asm volatile("cp.async.cg.shared.global [%0], [%1], 16;\n" :: "r"(s), "l"(src));
}
__device__ __forceinline__ void cp_commit() { asm volatile("cp.async.commit_group;\n"); }
template<int N>
__device__ __forceinline__ void cp_wait() { asm volatile("cp.async.wait_group %0;\n" :: "n"(N)); }

__device__ __forceinline__ float tf32_rnaf(float x) {
    unsigned r;
    asm("cvt.rna.tf32.f32 %0, %1;" : "=r"(r) : "f"(x));
    return __uint_as_float(r);
}
__device__ __forceinline__ void mma_tf32(float4& d, const uint4& a,
                                         unsigned b0, unsigned b1) {
    asm volatile(
        "mma.sync.aligned.m16n8k8.row.col.f32.tf32.tf32.f32 "
        "{%0,%1,%2,%3}, {%4,%5,%6,%7}, {%8,%9}, {%0,%1,%2,%3};"
        : "+f"(d.x), "+f"(d.y), "+f"(d.z), "+f"(d.w)
        : "r"(a.x), "r"(a.y), "r"(a.z), "r"(a.w), "r"(b0), "r"(b1));
}
// fp16 MMA, fp32 accumulate: A 4 regs (16x16 f16), B 2 regs (16x8 f16)
__device__ __forceinline__ void mma_f16(float4& d, const uint4& a,
                                        unsigned b0, unsigned b1) {
    asm volatile(
        "mma.sync.aligned.m16n8k16.row.col.f32.f16.f16.f32 "
        "{%0,%1,%2,%3}, {%4,%5,%6,%7}, {%8,%9}, {%0,%1,%2,%3};"
        : "+f"(d.x), "+f"(d.y), "+f"(d.z), "+f"(d.w)
        : "r"(a.x), "r"(a.y), "r"(a.z), "r"(a.w), "r"(b0), "r"(b1));
}
__device__ __forceinline__ float sigmoid_f(float x) {
    return __fdividef(1.0f, 1.0f + __expf(-x));
}
__device__ __forceinline__ float tanh_f(float x) {
    return __fdividef(2.0f, 1.0f + __expf(-2.0f * x)) - 1.0f;
}
__device__ __forceinline__ unsigned pack_h2(float lo, float hi) {
    __half2 h2 = __floats2half2_rn(lo, hi);
    return *reinterpret_cast<unsigned*>(&h2);
}

// hierarchical arrive: ~24 serialized atomic slots instead of 128.
__device__ __forceinline__ void bar_arrive(int bIdx) {
    __threadfence();                               // release prior global stores
    unsigned o = atomicAdd(&g_cnt1[bIdx >> 4].v, 1u);
    if (o == 15u) {
        unsigned o2 = atomicAdd(&g_cnt2, 1u);
        if (o2 == 7u) {
            #pragma unroll
            for (int i = 0; i < 8; i++) atomicExch(&g_cnt1[i].v, 0u);
            atomicExch(&g_cnt2, 0u);
            __threadfence();
            atomicAdd(&g_bar_gen, 1u);
        }
    }
}

// ============================================================================
// P1: permute xs -> g_xsA (A-frag tf32 layout).  (round-8, proven)
// ============================================================================
__global__ void __launch_bounds__(256) permA_kernel(const float* __restrict__ xs) {
    size_t x = (size_t)blockIdx.x * 256 + threadIdx.x;   // < 2048*128*32
    int lane  = (int)(x & 31);
    int ki    = (int)((x >> 5) & 127);
    int strip = (int)(x >> 12);
    int r  = strip * 16 + (lane >> 2);
    int k  = ki * 8 + (lane & 3);
    auto src = [&](int m, int kk) -> float {
        int b = m & 63, t = m >> 6;
        return xs[((size_t)b * T_ + t) * D_ + kk];
    };
    float4 v;
    v.x = tf32_rnaf(src(r,     k));
    v.y = tf32_rnaf(src(r + 8, k));
    v.z = tf32_rnaf(src(r,     k + 4));
    v.w = tf32_rnaf(src(r + 8, k + 4));
    *reinterpret_cast<float4*>(g_xsA + x * 4) = v;
}

// ============================================================================
// P2: permute Wx -> g_WxB (B-frag tf32 layout).  (round-8, proven)
// ============================================================================
__global__ void __launch_bounds__(256) permB_kernel(const float* __restrict__ Wx) {
    size_t y = (size_t)blockIdx.x * 256 + threadIdx.x;   // < 128*128*2*32
    int lane = (int)(y & 31);
    int nh   = (int)((y >> 5) & 1);
    int ki   = (int)((y >> 6) & 127);
    int ng   = (int)(y >> 13);
    int c = ng * 32 + nh * 16 + (lane >> 2);
    int k = ki * 8 + (lane & 3);
    float4 v;
    v.x = tf32_rnaf(Wx[(size_t)k * G4_ + c]);
    v.y = tf32_rnaf(Wx[(size_t)(k + 4) * G4_ + c]);
    v.z = tf32_rnaf(Wx[(size_t)k * G4_ + c + 8]);
    v.w = tf32_rnaf(Wx[(size_t)(k + 4) * G4_ + c + 8]);
    *reinterpret_cast<float4*>(g_WxB + y * 4) = v;
}

// ============================================================================
// Kernel G: xproj = xsA @ WxB  (round-8, proven, byte-identical)
// ============================================================================
__global__ void __launch_bounds__(256) xproj_kernel() {
    extern __shared__ float4 smG[];   // 3 stages x (A 2048 + B 2048) f4
    const int tid  = threadIdx.x;
    const int lane = tid & 31;
    const int w    = tid >> 5;
    const int wm   = w >> 2;
    const int wn   = w & 3;
    const int mt   = blockIdx.y;
    const int nt   = blockIdx.x;

    const float4* xsA = reinterpret_cast<const float4*>(g_xsA);
    const float4* WxB = reinterpret_cast<const float4*>(g_WxB);

    auto issue = [&](int ch) {
        float4* stA = smG + (ch % 3) * 4096;
        float4* stB = stA + 2048;
        #pragma unroll
        for (int it = 0; it < 8; it++) {
            int lin = tid + it * 256;
            int ln  = lin & 31;
            int dki = (lin >> 5) & 7;
            int st  = lin >> 8;
            cp_async16(&stA[lin],
                       &xsA[((size_t)(mt * 8 + st) * 128 + ch * 8 + dki) * 32 + ln]);
        }
        #pragma unroll
        for (int it = 0; it < 8; it++) {
            int lin = tid + it * 256;
            int ln  = lin & 31;
            int nh  = (lin >> 5) & 1;
            int dki = (lin >> 6) & 7;
            int ng  = lin >> 9;
            cp_async16(&stB[lin],
                       &WxB[(((size_t)(nt * 4 + ng) * 128 + ch * 8 + dki) * 2 + nh) * 32 + ln]);
        }
    };

    float4 acc[4][4];
    #pragma unroll
    for (int s = 0; s < 4; s++)
        #pragma unroll
        for (int g = 0; g < 4; g++)
            acc[s][g] = make_float4(0.f, 0.f, 0.f, 0.f);

    issue(0); cp_commit();
    issue(1); cp_commit();

    #pragma unroll 1
    for (int ch = 0; ch < 16; ch++) {
        __syncthreads();
        if (ch + 2 < 16) { issue(ch + 2); cp_commit(); }
        if (ch < 14) cp_wait<2>(); else if (ch == 14) cp_wait<1>(); else cp_wait<0>();
        __syncthreads();

        const float4* stA = smG + (ch % 3) * 4096;
        const float4* stB = stA + 2048;
        #pragma unroll
        for (int d = 0; d < 8; d++) {
            uint4 a[4];
            #pragma unroll
            for (int s = 0; s < 4; s++)
                a[s] = *reinterpret_cast<const uint4*>(
                    &stA[((wm * 4 + s) * 8 + d) * 32 + lane]);
            uint4 b0 = *reinterpret_cast<const uint4*>(&stB[((wn * 8 + d) * 2 + 0) * 32 + lane]);
            uint4 b1 = *reinterpret_cast<const uint4*>(&stB[((wn * 8 + d) * 2 + 1) * 32 + lane]);
            #pragma unroll
            for (int s = 0; s < 4; s++) {
                mma_tf32(acc[s][0], a[s], b0.x, b0.y);
                mma_tf32(acc[s][1], a[s], b0.z, b0.w);
                mma_tf32(acc[s][2], a[s], b1.x, b1.y);
                mma_tf32(acc[s][3], a[s], b1.z, b1.w);
            }
        }
    }

    int r  = lane >> 2;
    int c2 = (lane & 3) * 2;
    #pragma unroll
    for (int s = 0; s < 4; s++)
        #pragma unroll
        for (int g = 0; g < 4; g++) {
            size_t row = (size_t)mt * 128 + (wm * 4 + s) * 16 + r;
            size_t col = (size_t)nt * 128 + wn * 32 + g * 8 + c2;
            *reinterpret_cast<float2*>(g_xproj + row * G4_ + col) =
                make_float2(acc[s][g].x, acc[s][g].y);
            *reinterpret_cast<float2*>(g_xproj + (row + 8) * G4_ + col) =
                make_float2(acc[s][g].z, acc[s][g].w);
        }
}

// ============================================================================
// Kernel B: persistent LSTM scan, 128 blocks x 128 thr (4 warps), FP16 MMA.
//   Structure identical to round 7/8 (k-quarter warps, warp-local cp.async
//   pipeline with no in-loop syncthreads, sg reduce, hierarchical barrier);
//   datapath switched to m16n8k16.f16 with fp32 accumulate:
//     - h stored fp16 in mma-A layout (128KB/step broadcast, was 256KB)
//     - Whs fp16 B-frag, gate-grouped: uint4 = {b0,b1 of gate 2p; of 2p+1}
//     - per ki(k16): 4 A LDS.128 + 2 B LDS.128 -> 16 MMAs; 16 ki per warp
//   Accumulator layout == m16n8k8 -> sg staging/reduce byte-identical to R8.
// ============================================================================
__global__ void __launch_bounds__(128, 1) lstm_scan_kernel(
    const float* __restrict__ c0, const float* __restrict__ h0,
    const float* __restrict__ Wh, const float* __restrict__ bias,
    float* __restrict__ out)
{
    extern __shared__ float sm[];
    // Whs: uint4[4096] = 64KB, layout [kq(4)][ki2(16)][p(2)][lane(32)]
    uint4* Whs4 = reinterpret_cast<uint4*>(sm);
    // hs: uint4[4096] = 64KB, [kq(4)][stage(4)][dki(2)][strip(4)][lane(32)]
    uint4* hs4  = reinterpret_cast<uint4*>(sm + 16384);
    // sg: [kq(4)][row(64) stride 34] = 8704 floats
    float* sg   = sm + 32768;

    const int tid  = threadIdx.x;
    const int lane = tid & 31;
    const int kq   = tid >> 5;          // warp id == k-quarter (256 k each)
    const int bIdx = blockIdx.x;
    const int j0   = bIdx * 8;

    // ---- build Whs (fp16 B-frag, gate-grouped):
    //   uint4 i: lane=i&31, p=(i>>5)&1, ki2=(i>>6)&15, kq=i>>10
    //   word w: gate gidx = 2p + (w>>1), breg = w&1
    //   halves: {Wh[kb+tk+8*breg][gidx*H + j0 + n], Wh[kb+tk+8*breg+1][same]}
    //   kb = kq*256 + ki2*16, tk = (lane&3)*2, n = lane>>2
    for (int i = tid; i < 4096; i += 128) {
        int ln  = i & 31;
        int p   = (i >> 5) & 1;
        int ki2 = (i >> 6) & 15;
        int kqq = i >> 10;
        int tk = (ln & 3) * 2;
        int n  = ln >> 2;
        int kb = kqq * 256 + ki2 * 16;
        unsigned wd[4];
        #pragma unroll
        for (int w = 0; w < 4; w++) {
            int gidx = 2 * p + (w >> 1);
            int krow = kb + tk + 8 * (w & 1);
            const float* colp = Wh + (size_t)gidx * H_ + j0 + n;
            wd[w] = pack_h2(__ldg(colp + (size_t)krow * G4_),
                            __ldg(colp + (size_t)(krow + 1) * G4_));
        }
        Whs4[i] = make_uint4(wd[0], wd[1], wd[2], wd[3]);
    }

    // ---- per-thread ownership: column j = j0 + (tid&7), rows b_q = rbase+16q
    const int rbase = tid >> 3;         // 0..15
    const int jj    = tid & 7;
    const int j     = j0 + jj;
    int bq[4];
    #pragma unroll
    for (int q = 0; q < 4; q++) bq[q] = rbase + q * 16;

    float creg[4], bia[4];
    #pragma unroll
    for (int g = 0; g < 4; g++) bia[g] = __ldg(bias + g * H_ + j);
    #pragma unroll
    for (int q = 0; q < 4; q++) creg[q] = __ldg(c0 + (size_t)bq[q] * H_ + j);

    // ---- h write coords (fp16 layout). ki = bIdx>>1; strip == q.
    //   lane_w = (rbase&7)*4 + (jj>>1); v_w = (bIdx&1)*2 + (rbase>>3); hi = jj&1
    const int ki_w   = bIdx >> 1;
    const int lane_w = (rbase & 7) * 4 + (jj >> 1);
    const int v_w    = ((bIdx & 1) << 1) + (rbase >> 3);
    const int hi_w   = jj & 1;

    // ---- init g_hperm_h[0] = fp16(h0)
    #pragma unroll
    for (int q = 0; q < 4; q++) {
        size_t hidx = ((((size_t)ki_w * 4 + q) * 32 + lane_w) * 4 + v_w) * 2 + hi_w;
        g_hperm_h[0][hidx] = __float2half_rn(__ldg(h0 + (size_t)bq[q] * H_ + j));
    }

    // ---- xproj prefetch
    float xpr[4][4];
    auto prefetch_xp = [&](int t) {
        const float* xp = g_xproj + (size_t)t * B_ * G4_;
        #pragma unroll
        for (int q = 0; q < 4; q++)
            #pragma unroll
            for (int g = 0; g < 4; g++)
                xpr[q][g] = __ldg(xp + (size_t)bq[q] * G4_ + g * H_ + j);
    };
    prefetch_xp(0);

    // ---- initial global grid sync
    __syncthreads();
    {
        unsigned mygen = 0;
        if (tid == 0) {
            volatile unsigned* genp = &g_bar_gen;
            mygen = *genp;
            bar_arrive(bIdx);
            while (*genp == mygen) { }
            __threadfence();
        }
        __syncthreads();
    }

    for (int t = 0; t < T_; t++) {
        const uint4* hc4 = reinterpret_cast<const uint4*>(g_hperm_h[t & 1]);
        __half* hnext    = g_hperm_h[(t + 1) & 1];

        // warp-local issue of chunk ci (2 ki of this warp's quarter, 4KB)
        auto issue = [&](int ci) {
            uint4* dst = hs4 + kq * 1024 + (ci & 3) * 256;
            #pragma unroll
            for (int it = 0; it < 8; it++) {
                int dki   = it >> 2;
                int strip = it & 3;
                int ki    = kq * 16 + ci * 2 + dki;
                cp_async16(&dst[(dki * 4 + strip) * 32 + lane],
                           &hc4[((size_t)ki * 4 + strip) * 32 + lane]);
            }
        };

        issue(0); cp_commit();
        issue(1); cp_commit();
        issue(2); cp_commit();
        issue(3); cp_commit();

        float4 acc[4][4];   // [strip][gate]  (same layout as round 8)
        #pragma unroll
        for (int s = 0; s < 4; s++)
            #pragma unroll
            for (int g = 0; g < 4; g++)
                acc[s][g] = make_float4(0.f, 0.f, 0.f, 0.f);

        #pragma unroll 4
        for (int ch = 0; ch < 8; ch++) {
            if (ch < 5)       cp_wait<3>();
            else if (ch == 5) cp_wait<2>();
            else if (ch == 6) cp_wait<1>();
            else              cp_wait<0>();

            const uint4* st = hs4 + kq * 1024 + (ch & 3) * 256;
            #pragma unroll
            for (int d = 0; d < 2; d++) {
                int ki2 = ch * 2 + d;
                uint4 a[4];
                #pragma unroll
                for (int s = 0; s < 4; s++)
                    a[s] = st[(d * 4 + s) * 32 + lane];
                uint4 w0 = Whs4[((kq * 16 + ki2) * 2 + 0) * 32 + lane];
                uint4 w1 = Whs4[((kq * 16 + ki2) * 2 + 1) * 32 + lane];
                #pragma unroll
                for (int s = 0; s < 4; s++) {
                    mma_f16(acc[s][0], a[s], w0.x, w0.y);
                    mma_f16(acc[s][1], a[s], w0.z, w0.w);
                    mma_f16(acc[s][2], a[s], w1.x, w1.y);
                    mma_f16(acc[s][3], a[s], w1.z, w1.w);
                }
            }
            if (ch + 4 < 8) { issue(ch + 4); cp_commit(); }
        }

        // ---- stage partials: sg[kq][row (stride 34)][col = gate*8 + jj]
        {
            int r  = lane >> 2;
            int c2 = (lane & 3) * 2;
            float* base = sg + (size_t)kq * 64 * 34;
            #pragma unroll
            for (int s = 0; s < 4; s++)
                #pragma unroll
                for (int g = 0; g < 4; g++) {
                    *reinterpret_cast<float2*>(base + (s * 16 + r) * 34 + g * 8 + c2) =
                        make_float2(acc[s][g].x, acc[s][g].y);
                    *reinterpret_cast<float2*>(base + (s * 16 + r + 8) * 34 + g * 8 + c2) =
                        make_float2(acc[s][g].z, acc[s][g].w);
                }
        }
        __syncthreads();

        // ---- reduce 4 k-quarters + fused elementwise (flax order i,f,g,o)
        float hnv[4];
        #pragma unroll
        for (int q = 0; q < 4; q++) {
            float gv[4];
            #pragma unroll
            for (int g = 0; g < 4; g++) {
                float sum = 0.f;
                #pragma unroll
                for (int kk = 0; kk < 4; kk++)
                    sum += sg[((size_t)kk * 64 + bq[q]) * 34 + g * 8 + jj];
                gv[g] = sum;
            }
            float pi = gv[0] + xpr[q][0] + bia[0];
            float pf = gv[1] + xpr[q][1] + bia[1];
            float pg = gv[2] + xpr[q][2] + bia[2];
            float po = gv[3] + xpr[q][3] + bia[3];
            float cn = sigmoid_f(pf) * creg[q] + sigmoid_f(pi) * tanh_f(pg);
            float hn = sigmoid_f(po) * tanh_f(cn);
            creg[q] = cn;
            hnv[q] = hn;
        }

        // ---- write hnext (fp16, permuted)
        #pragma unroll
        for (int q = 0; q < 4; q++) {
            size_t hidx = ((((size_t)ki_w * 4 + q) * 32 + lane_w) * 4 + v_w) * 2 + hi_w;
            hnext[hidx] = __float2half_rn(hnv[q]);
        }

        // ---- barrier arrive (hierarchical; releases h stores)
        __syncthreads();
        unsigned mygen = 0;
        if (tid == 0) {
            volatile unsigned* genp = &g_bar_gen;
            mygen = *genp;
            bar_arrive(bIdx);
        }

        // ---- hidden work between arrive and wait: ys stores + next prefetch
        #pragma unroll
        for (int q = 0; q < 4; q++)
            out[2 * B_ * H_ + ((size_t)bq[q] * T_ + t) * H_ + j] = hnv[q];
        if (t == T_ - 1) {
            #pragma unroll
            for (int q = 0; q < 4; q++)
                out[B_ * H_ + (size_t)bq[q] * H_ + j] = hnv[q];
        }
        if (t + 1 < T_) prefetch_xp(t + 1);

        // ---- barrier wait
        if (tid == 0) {
            volatile unsigned* genp = &g_bar_gen;
            while (*genp == mygen) { }
            __threadfence();                    // acquire
        }
        __syncthreads();
    }

    // cT
    #pragma unroll
    for (int q = 0; q < 4; q++)
        out[(size_t)bq[q] * H_ + j] = creg[q];
}

// ============================================================================
// Launch. Inputs: c0, h0, xs, Wx, Wh, b. Output fp32: [cT][hT][ys]
// ============================================================================
extern "C" void kernel_launch(void* const* d_in, const int* in_sizes, int n_in,
                              void* d_out, int out_size) {
    const float* c0   = (const float*)d_in[0];
    const float* h0   = (const float*)d_in[1];
    const float* xs   = (const float*)d_in[2];
    const float* Wx   = (const float*)d_in[3];
    const float* Wh   = (const float*)d_in[4];
    const float* bias = (const float*)d_in[5];
    float* out = (float*)d_out;

    constexpr int G_SMEM    = 3 * 4096 * 16;                 // 196,608 B
    constexpr int SCAN_SMEM = (16384 + 16384 + 8704) * 4;    // 165,888 B
    cudaFuncSetAttribute(xproj_kernel,
                         cudaFuncAttributeMaxDynamicSharedMemorySize, G_SMEM);
    cudaFuncSetAttribute(lstm_scan_kernel,
                         cudaFuncAttributeMaxDynamicSharedMemorySize, SCAN_SMEM);

    permA_kernel<<<32768, 256>>>(xs);
    permB_kernel<<<4096, 256>>>(Wx);
    dim3 gridG(32, 256);
    xproj_kernel<<<gridG, 256, G_SMEM>>>();
    lstm_scan_kernel<<<128, 128, SCAN_SMEM>>>(c0, h0, Wh, bias, out);
}

// round 12
// speedup vs baseline: 1.7176x; 1.1685x over previous
#include <cuda_runtime.h>
#include <cuda_fp16.h>
#include <cstdint>
#include <math.h>

// Problem dims (SimpleLSTM): B=64, T=512, D=1024, H=1024
#define B_  64
#define T_  512
#define D_  1024
#define H_  1024
#define G4_ 4096   // 4*H

// ---------------- scratch (device globals: allocation-free) ----------------
__device__ float g_xproj[(size_t)T_ * B_ * G4_];      // [T*B][4H] fp32 (m = t*64+b)
// xs in fp16 A-frag (m16n8k16) layout: uint4 idx ((strip*64 + ki)*32 + lane)
__device__ __half g_xsA_h[(size_t)2048 * 64 * 32 * 8];   // 64MB
// Wx in fp16 B-frag pair layout: uint4 idx ((ng2*64 + ki)*32 + lane)
//   ng2 0..255 (2 n-octets each), words: {b0,b1 of ng2*2; b0,b1 of ng2*2+1}
__device__ __half g_WxB_h[(size_t)256 * 64 * 32 * 8];    // 8MB
// hidden state in fp16 A-frag layout (verified R10), double buffered
__device__ __half g_hperm_h[2][B_ * H_];

// hierarchical barrier state (counters return to 0 after each use -> replay-safe)
struct PadCnt { unsigned v; unsigned pad[31]; };   // 128B spacing
__device__ PadCnt g_cnt1[8];
__device__ unsigned g_cnt2 = 0;
__device__ unsigned g_bar_gen = 0;

// ---------------- helpers ----------------
__device__ __forceinline__ void cp_async16(void* dst, const void* src) {
    uint32_t s = (uint32_t)__cvta_generic_to_shared(dst);
    asm volatile("cp.async.cg.shared.global [%0], [%1], 16;\n" :: "r"(s), "l"(src));
}
__device__ __forceinline__ void cp_commit() { asm volatile("cp.async.commit_group;\n"); }
template<int N>
__device__ __forceinline__ void cp_wait() { asm volatile("cp.async.wait_group %0;\n" :: "n"(N)); }

// fp16 MMA, fp32 accumulate: A 4 regs (16x16 f16), B 2 regs (16x8 f16)
__device__ __forceinline__ void mma_f16(float4& d, const uint4& a,
                                        unsigned b0, unsigned b1) {
    asm volatile(
        "mma.sync.aligned.m16n8k16.row.col.f32.f16.f16.f32 "
        "{%0,%1,%2,%3}, {%4,%5,%6,%7}, {%8,%9}, {%0,%1,%2,%3};"
        : "+f"(d.x), "+f"(d.y), "+f"(d.z), "+f"(d.w)
        : "r"(a.x), "r"(a.y), "r"(a.z), "r"(a.w), "r"(b0), "r"(b1));
}
__device__ __forceinline__ float sigmoid_f(float x) {
    return __fdividef(1.0f, 1.0f + __expf(-x));
}
__device__ __forceinline__ float tanh_f(float x) {
    return __fdividef(2.0f, 1.0f + __expf(-2.0f * x)) - 1.0f;
}
__device__ __forceinline__ unsigned pack_h2(float lo, float hi) {
    __half2 h2 = __floats2half2_rn(lo, hi);
    return *reinterpret_cast<unsigned*>(&h2);
}

// hierarchical arrive: ~24 serialized atomic slots instead of 128.
__device__ __forceinline__ void bar_arrive(int bIdx) {
    __threadfence();                               // release prior global stores
    unsigned o = atomicAdd(&g_cnt1[bIdx >> 4].v, 1u);
    if (o == 15u) {
        unsigned o2 = atomicAdd(&g_cnt2, 1u);
        if (o2 == 7u) {
            #pragma unroll
            for (int i = 0; i < 8; i++) atomicExch(&g_cnt1[i].v, 0u);
            atomicExch(&g_cnt2, 0u);
            __threadfence();
            atomicAdd(&g_bar_gen, 1u);
        }
    }
}

// ============================================================================
// P1: permute xs -> g_xsA_h (fp16 A-frag layout).
//   uint4 x: lane=x&31, ki=(x>>5)&63, strip=x>>11.
//   r = strip*16 + (lane>>2), k = ki*16 + (lane&3)*2 ; m=r time-major.
// ============================================================================
__global__ void __launch_bounds__(256) permA_kernel(const float* __restrict__ xs) {
    size_t x = (size_t)blockIdx.x * 256 + threadIdx.x;   // < 4,194,304
    int lane  = (int)(x & 31);
    int ki    = (int)((x >> 5) & 63);
    int strip = (int)(x >> 11);
    int r  = strip * 16 + (lane >> 2);
    int k  = ki * 16 + (lane & 3) * 2;
    auto ld2 = [&](int m, int kk) -> unsigned {
        int b = m & 63, t = m >> 6;
        const float* p = xs + ((size_t)b * T_ + t) * D_ + kk;
        return pack_h2(p[0], p[1]);
    };
    uint4 v;
    v.x = ld2(r,     k);
    v.y = ld2(r + 8, k);
    v.z = ld2(r,     k + 8);
    v.w = ld2(r + 8, k + 8);
    reinterpret_cast<uint4*>(g_xsA_h)[x] = v;
}

// ============================================================================
// P2: permute Wx -> g_WxB_h (fp16 B-frag pair layout).
//   uint4 y: lane=y&31, ki=(y>>5)&63, ng2=y>>11.
//   word w: n-octet ng = ng2*2 + (w>>1), breg = w&1;
//   halves = {Wx[kb+tk+8*breg][ng*8+n], Wx[kb+tk+8*breg+1][same]}
//   kb = ki*16, tk = (lane&3)*2, n = lane>>2.
// ============================================================================
__global__ void __launch_bounds__(256) permB_kernel(const float* __restrict__ Wx) {
    size_t y = (size_t)blockIdx.x * 256 + threadIdx.x;   // < 524,288
    int lane = (int)(y & 31);
    int ki   = (int)((y >> 5) & 63);
    int ng2  = (int)(y >> 11);
    int tk = (lane & 3) * 2;
    int n  = lane >> 2;
    int kb = ki * 16;
    unsigned wd[4];
    #pragma unroll
    for (int w = 0; w < 4; w++) {
        int ng   = ng2 * 2 + (w >> 1);
        int krow = kb + tk + 8 * (w & 1);
        const float* colp = Wx + (size_t)ng * 8 + n;
        wd[w] = pack_h2(__ldg(colp + (size_t)krow * G4_),
                        __ldg(colp + (size_t)(krow + 1) * G4_));
    }
    reinterpret_cast<uint4*>(g_WxB_h)[y] = make_uint4(wd[0], wd[1], wd[2], wd[3]);
}

// ============================================================================
// Kernel G: xproj = xsA_h @ WxB_h  (M=32768, N=4096, K=1024), fp16 m16n8k16.
// 256 thr, 8 warps (wm 0..1 x wn 0..3), warp tile m64 x n32.
// Block tile 128x128, 8 k-chunks of 8 ki(16), 3-stage cp.async.
// Stage: A 2048 uint4 (8 strips x 8 ki x 32) + B 2048 uint4 (8 ng2 x 8 ki x 32)
// ============================================================================
__global__ void __launch_bounds__(256) xproj_kernel() {
    extern __shared__ uint4 smG[];   // 3 stages x 4096 uint4 = 196,608 B
    const int tid  = threadIdx.x;
    const int lane = tid & 31;
    const int w    = tid >> 5;
    const int wm   = w >> 2;    // 0..1
    const int wn   = w & 3;     // 0..3
    const int mt   = blockIdx.y;       // 0..255
    const int nt   = blockIdx.x;       // 0..31

    const uint4* xsA = reinterpret_cast<const uint4*>(g_xsA_h);
    const uint4* WxB = reinterpret_cast<const uint4*>(g_WxB_h);

    auto issue = [&](int ch) {
        uint4* stA = smG + (ch % 3) * 4096;
        uint4* stB = stA + 2048;
        #pragma unroll
        for (int it = 0; it < 8; it++) {            // A: 2048 uint4
            int lin = tid + it * 256;
            int ln  = lin & 31;
            int dki = (lin >> 5) & 7;
            int st  = lin >> 8;
            cp_async16(&stA[(st * 8 + dki) * 32 + ln],
                       &xsA[((size_t)(mt * 8 + st) * 64 + ch * 8 + dki) * 32 + ln]);
        }
        #pragma unroll
        for (int it = 0; it < 8; it++) {            // B: 2048 uint4
            int lin = tid + it * 256;
            int ln  = lin & 31;
            int dki = (lin >> 5) & 7;
            int lg  = lin >> 8;                     // local ng2 0..7
            cp_async16(&stB[(lg * 8 + dki) * 32 + ln],
                       &WxB[((size_t)(nt * 8 + lg) * 64 + ch * 8 + dki) * 32 + ln]);
        }
    };

    float4 acc[4][4];   // [strip][n-octet within warp]
    #pragma unroll
    for (int s = 0; s < 4; s++)
        #pragma unroll
        for (int g = 0; g < 4; g++)
            acc[s][g] = make_float4(0.f, 0.f, 0.f, 0.f);

    issue(0); cp_commit();
    issue(1); cp_commit();

    #pragma unroll 1
    for (int ch = 0; ch < 8; ch++) {
        __syncthreads();                       // readers of recycled stage done
        if (ch + 2 < 8) { issue(ch + 2); cp_commit(); }
        if (ch < 6) cp_wait<2>(); else if (ch == 6) cp_wait<1>(); else cp_wait<0>();
        __syncthreads();

        const uint4* stA = smG + (ch % 3) * 4096;
        const uint4* stB = stA + 2048;
        #pragma unroll
        for (int d = 0; d < 8; d++) {
            uint4 a[4];
            #pragma unroll
            for (int s = 0; s < 4; s++)
                a[s] = stA[((wm * 4 + s) * 8 + d) * 32 + lane];
            uint4 w0 = stB[((wn * 2 + 0) * 8 + d) * 32 + lane];
            uint4 w1 = stB[((wn * 2 + 1) * 8 + d) * 32 + lane];
            #pragma unroll
            for (int s = 0; s < 4; s++) {
                mma_f16(acc[s][0], a[s], w0.x, w0.y);
                mma_f16(acc[s][1], a[s], w0.z, w0.w);
                mma_f16(acc[s][2], a[s], w1.x, w1.y);
                mma_f16(acc[s][3], a[s], w1.z, w1.w);
            }
        }
    }

    // epilogue: fp32 rows to g_xproj. acc[s][g] covers rows (wm*4+s)*16 +r(+8),
    // cols (wn*4+g)*8 + c2(..+1) within the 128x128 tile.
    int r  = lane >> 2;
    int c2 = (lane & 3) * 2;
    #pragma unroll
    for (int s = 0; s < 4; s++)
        #pragma unroll
        for (int g = 0; g < 4; g++) {
            size_t row = (size_t)mt * 128 + (wm * 4 + s) * 16 + r;
            size_t col = (size_t)nt * 128 + (wn * 4 + g) * 8 + c2;
            *reinterpret_cast<float2*>(g_xproj + row * G4_ + col) =
                make_float2(acc[s][g].x, acc[s][g].y);
            *reinterpret_cast<float2*>(g_xproj + (row + 8) * G4_ + col) =
                make_float2(acc[s][g].z, acc[s][g].w);
        }
}

// ============================================================================
// Kernel B: persistent LSTM scan (round-10 version, PASSING, byte-identical).
// 128 blocks x 128 thr (4 warps), fp16 m16n8k16, warp-local cp.async pipeline,
// sg reduce, hierarchical barrier.
// ============================================================================
__global__ void __launch_bounds__(128, 1) lstm_scan_kernel(
    const float* __restrict__ c0, const float* __restrict__ h0,
    const float* __restrict__ Wh, const float* __restrict__ bias,
    float* __restrict__ out)
{
    extern __shared__ float sm[];
    uint4* Whs4 = reinterpret_cast<uint4*>(sm);            // 4096 uint4 = 64KB
    uint4* hs4  = reinterpret_cast<uint4*>(sm + 16384);    // 4096 uint4 = 64KB
    float* sg   = sm + 32768;                              // 8704 floats

    const int tid  = threadIdx.x;
    const int lane = tid & 31;
    const int kq   = tid >> 5;          // warp id == k-quarter (256 k each)
    const int bIdx = blockIdx.x;
    const int j0   = bIdx * 8;

    // ---- build Whs (fp16 B-frag, gate-grouped)
    for (int i = tid; i < 4096; i += 128) {
        int ln  = i & 31;
        int p   = (i >> 5) & 1;
        int ki2 = (i >> 6) & 15;
        int kqq = i >> 10;
        int tk = (ln & 3) * 2;
        int n  = ln >> 2;
        int kb = kqq * 256 + ki2 * 16;
        unsigned wd[4];
        #pragma unroll
        for (int w = 0; w < 4; w++) {
            int gidx = 2 * p + (w >> 1);
            int krow = kb + tk + 8 * (w & 1);
            const float* colp = Wh + (size_t)gidx * H_ + j0 + n;
            wd[w] = pack_h2(__ldg(colp + (size_t)krow * G4_),
                            __ldg(colp + (size_t)(krow + 1) * G4_));
        }
        Whs4[i] = make_uint4(wd[0], wd[1], wd[2], wd[3]);
    }

    // ---- per-thread ownership: column j = j0 + (tid&7), rows b_q = rbase+16q
    const int rbase = tid >> 3;
    const int jj    = tid & 7;
    const int j     = j0 + jj;
    int bq[4];
    #pragma unroll
    for (int q = 0; q < 4; q++) bq[q] = rbase + q * 16;

    float creg[4], bia[4];
    #pragma unroll
    for (int g = 0; g < 4; g++) bia[g] = __ldg(bias + g * H_ + j);
    #pragma unroll
    for (int q = 0; q < 4; q++) creg[q] = __ldg(c0 + (size_t)bq[q] * H_ + j);

    // ---- h write coords (fp16 layout)
    const int ki_w   = bIdx >> 1;
    const int lane_w = (rbase & 7) * 4 + (jj >> 1);
    const int v_w    = ((bIdx & 1) << 1) + (rbase >> 3);
    const int hi_w   = jj & 1;

    // ---- init g_hperm_h[0] = fp16(h0)
    #pragma unroll
    for (int q = 0; q < 4; q++) {
        size_t hidx = ((((size_t)ki_w * 4 + q) * 32 + lane_w) * 4 + v_w) * 2 + hi_w;
        g_hperm_h[0][hidx] = __float2half_rn(__ldg(h0 + (size_t)bq[q] * H_ + j));
    }

    // ---- xproj prefetch
    float xpr[4][4];
    auto prefetch_xp = [&](int t) {
        const float* xp = g_xproj + (size_t)t * B_ * G4_;
        #pragma unroll
        for (int q = 0; q < 4; q++)
            #pragma unroll
            for (int g = 0; g < 4; g++)
                xpr[q][g] = __ldg(xp + (size_t)bq[q] * G4_ + g * H_ + j);
    };
    prefetch_xp(0);

    // ---- initial global grid sync
    __syncthreads();
    {
        unsigned mygen = 0;
        if (tid == 0) {
            volatile unsigned* genp = &g_bar_gen;
            mygen = *genp;
            bar_arrive(bIdx);
            while (*genp == mygen) { }
            __threadfence();
        }
        __syncthreads();
    }

    for (int t = 0; t < T_; t++) {
        const uint4* hc4 = reinterpret_cast<const uint4*>(g_hperm_h[t & 1]);
        __half* hnext    = g_hperm_h[(t + 1) & 1];

        auto issue = [&](int ci) {
            uint4* dst = hs4 + kq * 1024 + (ci & 3) * 256;
            #pragma unroll
            for (int it = 0; it < 8; it++) {
                int dki   = it >> 2;
                int strip = it & 3;
                int ki    = kq * 16 + ci * 2 + dki;
                cp_async16(&dst[(dki * 4 + strip) * 32 + lane],
                           &hc4[((size_t)ki * 4 + strip) * 32 + lane]);
            }
        };

        issue(0); cp_commit();
        issue(1); cp_commit();
        issue(2); cp_commit();
        issue(3); cp_commit();

        float4 acc[4][4];   // [strip][gate]
        #pragma unroll
        for (int s = 0; s < 4; s++)
            #pragma unroll
            for (int g = 0; g < 4; g++)
                acc[s][g] = make_float4(0.f, 0.f, 0.f, 0.f);

        #pragma unroll 4
        for (int ch = 0; ch < 8; ch++) {
            if (ch < 5)       cp_wait<3>();
            else if (ch == 5) cp_wait<2>();
            else if (ch == 6) cp_wait<1>();
            else              cp_wait<0>();

            const uint4* st = hs4 + kq * 1024 + (ch & 3) * 256;
            #pragma unroll
            for (int d = 0; d < 2; d++) {
                int ki2 = ch * 2 + d;
                uint4 a[4];
                #pragma unroll
                for (int s = 0; s < 4; s++)
                    a[s] = st[(d * 4 + s) * 32 + lane];
                uint4 w0 = Whs4[((kq * 16 + ki2) * 2 + 0) * 32 + lane];
                uint4 w1 = Whs4[((kq * 16 + ki2) * 2 + 1) * 32 + lane];
                #pragma unroll
                for (int s = 0; s < 4; s++) {
                    mma_f16(acc[s][0], a[s], w0.x, w0.y);
                    mma_f16(acc[s][1], a[s], w0.z, w0.w);
                    mma_f16(acc[s][2], a[s], w1.x, w1.y);
                    mma_f16(acc[s][3], a[s], w1.z, w1.w);
                }
            }
            if (ch + 4 < 8) { issue(ch + 4); cp_commit(); }
        }

        // ---- stage partials: sg[kq][row (stride 34)][col = gate*8 + jj]
        {
            int r  = lane >> 2;
            int c2 = (lane & 3) * 2;
            float* base = sg + (size_t)kq * 64 * 34;
            #pragma unroll
            for (int s = 0; s < 4; s++)
                #pragma unroll
                for (int g = 0; g < 4; g++) {
                    *reinterpret_cast<float2*>(base + (s * 16 + r) * 34 + g * 8 + c2) =
                        make_float2(acc[s][g].x, acc[s][g].y);
                    *reinterpret_cast<float2*>(base + (s * 16 + r + 8) * 34 + g * 8 + c2) =
                        make_float2(acc[s][g].z, acc[s][g].w);
                }
        }
        __syncthreads();

        // ---- reduce 4 k-quarters + fused elementwise (flax order i,f,g,o)
        float hnv[4];
        #pragma unroll
        for (int q = 0; q < 4; q++) {
            float gv[4];
            #pragma unroll
            for (int g = 0; g < 4; g++) {
                float sum = 0.f;
                #pragma unroll
                for (int kk = 0; kk < 4; kk++)
                    sum += sg[((size_t)kk * 64 + bq[q]) * 34 + g * 8 + jj];
                gv[g] = sum;
            }
            float pi = gv[0] + xpr[q][0] + bia[0];
            float pf = gv[1] + xpr[q][1] + bia[1];
            float pg = gv[2] + xpr[q][2] + bia[2];
            float po = gv[3] + xpr[q][3] + bia[3];
            float cn = sigmoid_f(pf) * creg[q] + sigmoid_f(pi) * tanh_f(pg);
            float hn = sigmoid_f(po) * tanh_f(cn);
            creg[q] = cn;
            hnv[q] = hn;
        }

        // ---- write hnext (fp16, permuted)
        #pragma unroll
        for (int q = 0; q < 4; q++) {
            size_t hidx = ((((size_t)ki_w * 4 + q) * 32 + lane_w) * 4 + v_w) * 2 + hi_w;
            hnext[hidx] = __float2half_rn(hnv[q]);
        }

        // ---- barrier arrive (hierarchical; releases h stores)
        __syncthreads();
        unsigned mygen = 0;
        if (tid == 0) {
            volatile unsigned* genp = &g_bar_gen;
            mygen = *genp;
            bar_arrive(bIdx);
        }

        // ---- hidden work between arrive and wait: ys stores + next prefetch
        #pragma unroll
        for (int q = 0; q < 4; q++)
            out[2 * B_ * H_ + ((size_t)bq[q] * T_ + t) * H_ + j] = hnv[q];
        if (t == T_ - 1) {
            #pragma unroll
            for (int q = 0; q < 4; q++)
                out[B_ * H_ + (size_t)bq[q] * H_ + j] = hnv[q];
        }
        if (t + 1 < T_) prefetch_xp(t + 1);

        // ---- barrier wait
        if (tid == 0) {
            volatile unsigned* genp = &g_bar_gen;
            while (*genp == mygen) { }
            __threadfence();                    // acquire
        }
        __syncthreads();
    }

    // cT
    #pragma unroll
    for (int q = 0; q < 4; q++)
        out[(size_t)bq[q] * H_ + j] = creg[q];
}

// ============================================================================
// Launch. Inputs: c0, h0, xs, Wx, Wh, b. Output fp32: [cT][hT][ys]
// ============================================================================
extern "C" void kernel_launch(void* const* d_in, const int* in_sizes, int n_in,
                              void* d_out, int out_size) {
    const float* c0   = (const float*)d_in[0];
    const float* h0   = (const float*)d_in[1];
    const float* xs   = (const float*)d_in[2];
    const float* Wx   = (const float*)d_in[3];
    const float* Wh   = (const float*)d_in[4];
    const float* bias = (const float*)d_in[5];
    float* out = (float*)d_out;

    constexpr int G_SMEM    = 3 * 4096 * 16;                 // 196,608 B
    constexpr int SCAN_SMEM = (16384 + 16384 + 8704) * 4;    // 165,888 B
    cudaFuncSetAttribute(xproj_kernel,
                         cudaFuncAttributeMaxDynamicSharedMemorySize, G_SMEM);
    cudaFuncSetAttribute(lstm_scan_kernel,
                         cudaFuncAttributeMaxDynamicSharedMemorySize, SCAN_SMEM);

    permA_kernel<<<16384, 256>>>(xs);     // 4,194,304 uint4 / 256
    permB_kernel<<<2048, 256>>>(Wx);      // 524,288 uint4 / 256
    dim3 gridG(32, 256);
    xproj_kernel<<<gridG, 256, G_SMEM>>>();
    lstm_scan_kernel<<<128, 128, SCAN_SMEM>>>(c0, h0, Wh, bias, out);
}